// round 4
// baseline (speedup 1.0000x reference)
#include <cuda_runtime.h>
#include <math.h>

#define N      4096
#define D      128
#define NW     128          // 4096 bits / 32
#define MLP_R  16           // rows per MLP block
#define HOP_G  8            // rows per hop block
#define LISTCAP 2048
#define XSTRIDE 36          // dup-x smem row stride (floats), 144B = 16B-aligned

// ---------------- scratch (device globals) ----------------------------------
__device__ unsigned  g_A  [N * NW];
__device__ unsigned  g_A2 [N * NW];
__device__ float     g_Wt [3 * D * D];   // pre-transposed weights, k-major
__device__ float     g_a0[N];
__device__ float     g_av2[N];
__device__ long long g_stepq[N];
__device__ float     g_step[N];
__device__ int       g_is64;

#define FMA2(acc, w, x) asm("fma.rn.f32x2 %0, %1, %2, %0;" : "+l"(acc) : "l"(w), "l"(x))
union U64F2 { unsigned long long u; float2 f; };

// ---------------- prep: zero A/stepq + transpose W0..W2 + dtype detect ------
__global__ void prep_kernel(const float* __restrict__ W0,
                            const float* __restrict__ W1,
                            const float* __restrict__ W2,
                            const void* __restrict__ ei) {
    if (blockIdx.x == gridDim.x - 1) {
        __shared__ int bad;
        if (threadIdx.x == 0) bad = 0;
        __syncthreads();
        const long long* p = (const long long*)ei;
        for (int i = threadIdx.x; i < 2048; i += blockDim.x) {
            long long v = p[i];
            if (v < 0 || v >= N) bad = 1;
        }
        __syncthreads();
        if (threadIdx.x == 0) g_is64 = bad ? 0 : 1;
        return;
    }
    int idx = blockIdx.x * 256 + threadIdx.x;
    if (idx < N * NW) {
        g_A[idx] = 0u;
        if (idx < N) g_stepq[idx] = 0ll;
    } else {
        int t = idx - N * NW;
        int m  = t >> 14;
        int tp = t & 16383;                  // tp = k*128 + c
        int c  = tp & 127;
        int k  = tp >> 7;
        const float* Ws = (m == 0) ? W0 : (m == 1 ? W1 : W2);
        g_Wt[m * 16384 + tp] = Ws[c * 128 + k];
    }
}

// ---------------- fused MLP: 3 x (GEMM+ReLU) + final dot, one kernel --------
// 128 threads, 16 rows/block. Thread tile: 2 rows x 8 cols (4 FFMA2 pairs,
// cols cg*2+32j+{0,1}). X kept in smem pre-DUPLICATED ({x,x}) k-major so the
// inner loop needs no MOVs. W read via LDG.64 from L1-resident g_Wt.
__global__ __launch_bounds__(128, 4)
void mlp_kernel(const float* __restrict__ coeffs,
                const float* __restrict__ b0,
                const float* __restrict__ W3,
                const float* __restrict__ b3) {
    __shared__ float xa[128 * XSTRIDE];
    __shared__ float xb[128 * XSTRIDE];

    const int tid = threadIdx.x;
    const int r0  = blockIdx.x * MLP_R;
    const int rg  = tid >> 4;     // 8 row-groups of 2 rows
    const int cg  = tid & 15;     // 16 col-groups

    // stage coeffs dup-transposed into xa: xa[k*XS + 2r..2r+1] = {x,x}
    #pragma unroll
    for (int it = 0; it < 4; it++) {
        int idx = it * 128 + tid;           // 0..511
        int r  = idx >> 5;                  // 0..15
        int kq = idx & 31;                  // 0..31
        float4 v = *(const float4*)&coeffs[(r0 + r) * 128 + kq * 4];
        float vv[4] = {v.x, v.y, v.z, v.w};
        #pragma unroll
        for (int q = 0; q < 4; q++) {
            float2 dd = make_float2(vv[q], vv[q]);
            *(float2*)&xa[(kq * 4 + q) * XSTRIDE + 2 * r] = dd;
        }
    }
    __syncthreads();

    float* Xin  = xa;
    float* Xout = xb;

    #pragma unroll
    for (int layer = 0; layer < 3; layer++) {
        const float* Wl = g_Wt + layer * 16384;

        unsigned long long a0p[4], a1p[4];
        #pragma unroll
        for (int j = 0; j < 4; j++) { a0p[j] = 0ull; a1p[j] = 0ull; }

        #pragma unroll 8
        for (int k = 0; k < 128; k++) {
            ulonglong2 xx = *(const ulonglong2*)&Xin[k * XSTRIDE + rg * 4];
            const float* wrow = Wl + k * 128 + cg * 2;
            unsigned long long w0 = *(const unsigned long long*)(wrow);
            unsigned long long w1 = *(const unsigned long long*)(wrow + 32);
            unsigned long long w2 = *(const unsigned long long*)(wrow + 64);
            unsigned long long w3 = *(const unsigned long long*)(wrow + 96);
            FMA2(a0p[0], w0, xx.x); FMA2(a1p[0], w0, xx.y);
            FMA2(a0p[1], w1, xx.x); FMA2(a1p[1], w1, xx.y);
            FMA2(a0p[2], w2, xx.x); FMA2(a1p[2], w2, xx.y);
            FMA2(a0p[3], w3, xx.x); FMA2(a1p[3], w3, xx.y);
        }

        float o0[8], o1[8];
        #pragma unroll
        for (int j = 0; j < 4; j++) {
            U64F2 u0, u1; u0.u = a0p[j]; u1.u = a1p[j];
            o0[2 * j] = u0.f.x; o0[2 * j + 1] = u0.f.y;
            o1[2 * j] = u1.f.x; o1[2 * j + 1] = u1.f.y;
        }
        if (layer == 0) {
            #pragma unroll
            for (int j = 0; j < 4; j++) {
                float2 bb = *(const float2*)&b0[32 * j + cg * 2];
                o0[2 * j] += bb.x; o0[2 * j + 1] += bb.y;
                o1[2 * j] += bb.x; o1[2 * j + 1] += bb.y;
            }
        }
        #pragma unroll
        for (int j = 0; j < 8; j++) {
            o0[j] = fmaxf(o0[j], 0.f);
            o1[j] = fmaxf(o1[j], 0.f);
        }

        if (layer < 2) {
            // write dup-transposed into Xout (k-row = col index)
            #pragma unroll
            for (int j = 0; j < 4; j++) {
                int k0 = cg * 2 + 32 * j;
                *(float2*)&Xout[(k0    ) * XSTRIDE + 4 * rg    ] = make_float2(o0[2*j],   o0[2*j]);
                *(float2*)&Xout[(k0 + 1) * XSTRIDE + 4 * rg    ] = make_float2(o0[2*j+1], o0[2*j+1]);
                *(float2*)&Xout[(k0    ) * XSTRIDE + 4 * rg + 2] = make_float2(o1[2*j],   o1[2*j]);
                *(float2*)&Xout[(k0 + 1) * XSTRIDE + 4 * rg + 2] = make_float2(o1[2*j+1], o1[2*j+1]);
            }
            __syncthreads();
            float* tmp = Xin; Xin = Xout; Xout = tmp;
        } else {
            // fused final layer: dot with W3, reduce over 16 lanes of this rg
            float p0 = 0.f, p1 = 0.f;
            #pragma unroll
            for (int j = 0; j < 4; j++) {
                float2 w3v = *(const float2*)&W3[32 * j + cg * 2];
                p0 = fmaf(o0[2*j], w3v.x, fmaf(o0[2*j+1], w3v.y, p0));
                p1 = fmaf(o1[2*j], w3v.x, fmaf(o1[2*j+1], w3v.y, p1));
            }
            #pragma unroll
            for (int off = 8; off; off >>= 1) {
                p0 += __shfl_down_sync(0xffffffffu, p0, off, 16);
                p1 += __shfl_down_sync(0xffffffffu, p1, off, 16);
            }
            if (cg == 0) {
                float bb = b3[0];
                g_a0[r0 + rg * 2]     = p0 + bb;
                g_a0[r0 + rg * 2 + 1] = p1 + bb;
            }
        }
    }
}

// ---------------- edges: bitset build + hop-1 scatter (duplicates kept) -----
__global__ void edge_kernel(const void* __restrict__ ei, int ne) {
    int e = blockIdx.x * blockDim.x + threadIdx.x;
    if (e >= ne) return;
    int row, col;
    if (g_is64) {
        const long long* p = (const long long*)ei;
        row = (int)p[e];
        col = (int)p[ne + e];
    } else {
        const int* p = (const int*)ei;
        row = p[e];
        col = p[ne + e];
    }
    atomicOr(&g_A[row * NW + (col >> 5)], 1u << (col & 31));
    float v = 0.69314718055994531f * g_a0[col];
    long long q = __float2ll_rn(v * 4294967296.0f);
    atomicAdd((unsigned long long*)&g_stepq[row], (unsigned long long)q);
}

// ---------------- fused boolmm + gated matvec (uint2 path) -------------------
// 256 threads = 4 groups x 64; each group handles one row per pass (2 words
// per thread). vec staged in smem; dense words use complement trick.
// phase 0 computes a1 inline from a0+stepq (finish_hop1 folded in).
__global__ __launch_bounds__(256)
void fused_hop_kernel(int phase, float* __restrict__ out_final) {
    const unsigned* M = phase ? g_A2 : g_A;

    const int tid = threadIdx.x;
    const int g   = tid >> 6;      // group 0..3
    const int t   = tid & 63;      // word-pair index
    const int i0  = blockIdx.x * HOP_G;

    __shared__ float          vsh[4096];
    __shared__ float          psum[256];
    __shared__ float          seg[64];
    __shared__ unsigned short list[4][LISTCAP];
    __shared__ int            cnt[4];
    __shared__ float          part[8];

    // stage vec + partial sums
    {
        float s = 0.f;
        #pragma unroll 4
        for (int q = 0; q < 16; q++) {
            int idx = tid * 16 + q;
            float v;
            if (phase) v = g_av2[idx];
            else       v = g_a0[idx] +
                           (float)((double)g_stepq[idx] * (1.0 / 4294967296.0));
            vsh[idx] = v;
            s += v;
        }
        psum[tid] = s;
    }
    __syncthreads();
    if (tid < 64)
        seg[tid] = (psum[4 * tid] + psum[4 * tid + 1]) +
                   (psum[4 * tid + 2] + psum[4 * tid + 3]);

    for (int pass = 0; pass < HOP_G / 4; pass++) {
        const int i = i0 + pass * 4 + g;
        if (t == 0) cnt[g] = 0;
        __syncthreads();

        // extract neighbor list of row i (2 words per thread)
        uint2 mw = *(const uint2*)&g_A[i * NW + 2 * t];
        int nb = __popc(mw.x) + __popc(mw.y);
        int pos = nb ? atomicAdd(&cnt[g], nb) : 0;
        {
            unsigned mm = mw.x; int jb = t * 64;
            while (mm) {
                int b = __ffs((int)mm) - 1; mm &= mm - 1;
                if (pos < LISTCAP) list[g][pos] = (unsigned short)(jb + b);
                pos++;
            }
            mm = mw.y; jb = t * 64 + 32;
            while (mm) {
                int b = __ffs((int)mm) - 1; mm &= mm - 1;
                if (pos < LISTCAP) list[g][pos] = (unsigned short)(jb + b);
                pos++;
            }
        }
        __syncthreads();

        const int c = min(cnt[g], LISTCAP);
        unsigned ax = 0u, ay = 0u;
        int j = 0;
        for (; j + 4 <= c; j += 4) {
            uint2 q0 = *(const uint2*)&M[(int)list[g][j]     * NW + 2 * t];
            uint2 q1 = *(const uint2*)&M[(int)list[g][j + 1] * NW + 2 * t];
            uint2 q2 = *(const uint2*)&M[(int)list[g][j + 2] * NW + 2 * t];
            uint2 q3 = *(const uint2*)&M[(int)list[g][j + 3] * NW + 2 * t];
            ax |= (q0.x | q1.x) | (q2.x | q3.x);
            ay |= (q0.y | q1.y) | (q2.y | q3.y);
        }
        for (; j < c; j++) {
            uint2 q = *(const uint2*)&M[(int)list[g][j] * NW + 2 * t];
            ax |= q.x; ay |= q.y;
        }
        if (cnt[g] > LISTCAP) {          // overflow fallback (OR idempotent)
            for (int ww = 0; ww < NW; ww++) {
                unsigned mm = g_A[i * NW + ww];
                int jb = ww * 32;
                while (mm) {
                    int b = __ffs((int)mm) - 1; mm &= mm - 1;
                    uint2 q = *(const uint2*)&M[(jb + b) * NW + 2 * t];
                    ax |= q.x; ay |= q.y;
                }
            }
        }

        if (!phase) *(uint2*)&g_A2[i * NW + 2 * t] = make_uint2(ax, ay);

        // gated sum over the 64-float segment
        const float* base = vsh + t * 64;
        int pc = __popc(ax) + __popc(ay);
        float sv;
        if (pc > 32) {
            sv = seg[t];
            unsigned m = ~ax;
            while (m) { int b = __ffs((int)m) - 1; m &= m - 1; sv -= base[b]; }
            m = ~ay;
            while (m) { int b = __ffs((int)m) - 1; m &= m - 1; sv -= base[32 + b]; }
        } else {
            sv = 0.f;
            unsigned m = ax;
            while (m) { int b = __ffs((int)m) - 1; m &= m - 1; sv += base[b]; }
            m = ay;
            while (m) { int b = __ffs((int)m) - 1; m &= m - 1; sv += base[32 + b]; }
        }
        #pragma unroll
        for (int off = 16; off; off >>= 1)
            sv += __shfl_down_sync(0xffffffffu, sv, off);
        if ((tid & 31) == 0) part[tid >> 5] = sv;
        __syncthreads();

        if (t == 0) {
            float tot = part[2 * g] + part[2 * g + 1];
            if (!phase) {
                float s1 = (float)((double)g_stepq[i] * (1.0 / 4294967296.0));
                float ns = s1 + 1.0986122886681098f * tot;     // ln 3
                g_step[i] = ns;
                g_av2[i]  = (g_a0[i] + s1) + ns;
            } else {
                out_final[i] = g_av2[i] + g_step[i] + 1.3862943611198906f * tot; // ln 4
            }
        }
        __syncthreads();
    }
}

// ---------------- launch ----------------------------------------------------
extern "C" void kernel_launch(void* const* d_in, const int* in_sizes, int n_in,
                              void* d_out, int out_size) {
    const float* coeffs = (const float*)d_in[0];
    const void*  ei     = d_in[1];
    const float* W0     = (const float*)d_in[2];
    const float* b0     = (const float*)d_in[3];
    const float* W1     = (const float*)d_in[4];
    const float* W2     = (const float*)d_in[5];
    const float* W3     = (const float*)d_in[6];
    const float* b3     = (const float*)d_in[7];
    float* out = (float*)d_out;

    const int ne = in_sizes[1] / 2;

    const int prep_blocks = (N * NW + 3 * 16384) / 256 + 1;
    prep_kernel<<<prep_blocks, 256>>>(W0, W1, W2, ei);

    mlp_kernel<<<N / MLP_R, 128>>>(coeffs, b0, W3, b3);

    edge_kernel<<<(ne + 255) / 256, 256>>>(ei, ne);

    fused_hop_kernel<<<N / HOP_G, 256>>>(0, out);
    fused_hop_kernel<<<N / HOP_G, 256>>>(1, out);
}

// round 5
// speedup vs baseline: 1.1461x; 1.1461x over previous
#include <cuda_runtime.h>
#include <math.h>

#define N      4096
#define D      128
#define NW     128          // 4096 bits / 32
#define MLP_R  16           // rows per MLP block
#define WCAP   320          // per-warp neighbor list capacity
#define XSTRIDE 36          // dup-x smem row stride (floats)

// ---------------- scratch (device globals) ----------------------------------
__device__ unsigned  g_A  [N * NW];
__device__ unsigned  g_A2 [N * NW];
__device__ float     g_Wt [3 * D * D];   // pre-transposed weights, k-major
__device__ float     g_a0[N];
__device__ float     g_av2[N];
__device__ long long g_stepq[N];
__device__ float     g_step[N];
__device__ int       g_is64;

#define FMA2(acc, w, x) asm("fma.rn.f32x2 %0, %1, %2, %0;" : "+l"(acc) : "l"(w), "l"(x))
union U64F2 { unsigned long long u; float2 f; };

__device__ __forceinline__ int popc4(uint4 v) {
    return __popc(v.x) + __popc(v.y) + __popc(v.z) + __popc(v.w);
}

// ---------------- prep: zero A/stepq + transpose W0..W2 + dtype detect ------
__global__ void prep_kernel(const float* __restrict__ W0,
                            const float* __restrict__ W1,
                            const float* __restrict__ W2,
                            const void* __restrict__ ei) {
    if (blockIdx.x == gridDim.x - 1) {
        __shared__ int bad;
        if (threadIdx.x == 0) bad = 0;
        __syncthreads();
        const long long* p = (const long long*)ei;
        for (int i = threadIdx.x; i < 2048; i += blockDim.x) {
            long long v = p[i];
            if (v < 0 || v >= N) bad = 1;
        }
        __syncthreads();
        if (threadIdx.x == 0) g_is64 = bad ? 0 : 1;
        return;
    }
    int idx = blockIdx.x * 256 + threadIdx.x;
    if (idx < N * NW) {
        g_A[idx] = 0u;
        if (idx < N) g_stepq[idx] = 0ll;
    } else {
        int t = idx - N * NW;
        int m  = t >> 14;
        int tp = t & 16383;                  // tp = k*128 + c
        int c  = tp & 127;
        int k  = tp >> 7;
        const float* Ws = (m == 0) ? W0 : (m == 1 ? W1 : W2);
        g_Wt[m * 16384 + tp] = Ws[c * 128 + k];
    }
}

// ---------------- fused MLP: 3 x (GEMM+ReLU) + final dot, one kernel --------
__global__ __launch_bounds__(128, 4)
void mlp_kernel(const float* __restrict__ coeffs,
                const float* __restrict__ b0,
                const float* __restrict__ W3,
                const float* __restrict__ b3) {
    __shared__ float xa[128 * XSTRIDE];
    __shared__ float xb[128 * XSTRIDE];

    const int tid = threadIdx.x;
    const int r0  = blockIdx.x * MLP_R;
    const int rg  = tid >> 4;     // 8 row-groups of 2 rows
    const int cg  = tid & 15;     // 16 col-groups

    #pragma unroll
    for (int it = 0; it < 4; it++) {
        int idx = it * 128 + tid;
        int r  = idx >> 5;
        int kq = idx & 31;
        float4 v = *(const float4*)&coeffs[(r0 + r) * 128 + kq * 4];
        float vv[4] = {v.x, v.y, v.z, v.w};
        #pragma unroll
        for (int q = 0; q < 4; q++)
            *(float2*)&xa[(kq * 4 + q) * XSTRIDE + 2 * r] = make_float2(vv[q], vv[q]);
    }
    __syncthreads();

    float* Xin  = xa;
    float* Xout = xb;

    #pragma unroll
    for (int layer = 0; layer < 3; layer++) {
        const float* Wl = g_Wt + layer * 16384;

        unsigned long long a0p[4], a1p[4];
        #pragma unroll
        for (int j = 0; j < 4; j++) { a0p[j] = 0ull; a1p[j] = 0ull; }

        #pragma unroll 8
        for (int k = 0; k < 128; k++) {
            ulonglong2 xx = *(const ulonglong2*)&Xin[k * XSTRIDE + rg * 4];
            const float* wrow = Wl + k * 128 + cg * 2;
            unsigned long long w0 = *(const unsigned long long*)(wrow);
            unsigned long long w1 = *(const unsigned long long*)(wrow + 32);
            unsigned long long w2 = *(const unsigned long long*)(wrow + 64);
            unsigned long long w3 = *(const unsigned long long*)(wrow + 96);
            FMA2(a0p[0], w0, xx.x); FMA2(a1p[0], w0, xx.y);
            FMA2(a0p[1], w1, xx.x); FMA2(a1p[1], w1, xx.y);
            FMA2(a0p[2], w2, xx.x); FMA2(a1p[2], w2, xx.y);
            FMA2(a0p[3], w3, xx.x); FMA2(a1p[3], w3, xx.y);
        }

        float o0[8], o1[8];
        #pragma unroll
        for (int j = 0; j < 4; j++) {
            U64F2 u0, u1; u0.u = a0p[j]; u1.u = a1p[j];
            o0[2 * j] = u0.f.x; o0[2 * j + 1] = u0.f.y;
            o1[2 * j] = u1.f.x; o1[2 * j + 1] = u1.f.y;
        }
        if (layer == 0) {
            #pragma unroll
            for (int j = 0; j < 4; j++) {
                float2 bb = *(const float2*)&b0[32 * j + cg * 2];
                o0[2 * j] += bb.x; o0[2 * j + 1] += bb.y;
                o1[2 * j] += bb.x; o1[2 * j + 1] += bb.y;
            }
        }
        #pragma unroll
        for (int j = 0; j < 8; j++) {
            o0[j] = fmaxf(o0[j], 0.f);
            o1[j] = fmaxf(o1[j], 0.f);
        }

        if (layer < 2) {
            #pragma unroll
            for (int j = 0; j < 4; j++) {
                int k0 = cg * 2 + 32 * j;
                *(float2*)&Xout[(k0    ) * XSTRIDE + 4 * rg    ] = make_float2(o0[2*j],   o0[2*j]);
                *(float2*)&Xout[(k0 + 1) * XSTRIDE + 4 * rg    ] = make_float2(o0[2*j+1], o0[2*j+1]);
                *(float2*)&Xout[(k0    ) * XSTRIDE + 4 * rg + 2] = make_float2(o1[2*j],   o1[2*j]);
                *(float2*)&Xout[(k0 + 1) * XSTRIDE + 4 * rg + 2] = make_float2(o1[2*j+1], o1[2*j+1]);
            }
            __syncthreads();
            float* tmp = Xin; Xin = Xout; Xout = tmp;
        } else {
            float p0 = 0.f, p1 = 0.f;
            #pragma unroll
            for (int j = 0; j < 4; j++) {
                float2 w3v = *(const float2*)&W3[32 * j + cg * 2];
                p0 = fmaf(o0[2*j], w3v.x, fmaf(o0[2*j+1], w3v.y, p0));
                p1 = fmaf(o1[2*j], w3v.x, fmaf(o1[2*j+1], w3v.y, p1));
            }
            #pragma unroll
            for (int off = 8; off; off >>= 1) {
                p0 += __shfl_down_sync(0xffffffffu, p0, off, 16);
                p1 += __shfl_down_sync(0xffffffffu, p1, off, 16);
            }
            if (cg == 0) {
                float bb = b3[0];
                g_a0[r0 + rg * 2]     = p0 + bb;
                g_a0[r0 + rg * 2 + 1] = p1 + bb;
            }
        }
    }
}

// ---------------- edges: bitset build + hop-1 scatter (duplicates kept) -----
__global__ void edge_kernel(const void* __restrict__ ei, int ne) {
    int e = blockIdx.x * blockDim.x + threadIdx.x;
    if (e >= ne) return;
    int row, col;
    if (g_is64) {
        const long long* p = (const long long*)ei;
        row = (int)p[e];
        col = (int)p[ne + e];
    } else {
        const int* p = (const int*)ei;
        row = p[e];
        col = p[ne + e];
    }
    atomicOr(&g_A[row * NW + (col >> 5)], 1u << (col & 31));
    float v = 0.69314718055994531f * g_a0[col];
    long long q = __float2ll_rn(v * 4294967296.0f);
    atomicAdd((unsigned long long*)&g_stepq[row], (unsigned long long)q);
}

// ---------------- fused boolmm + gated matvec: warp-per-row, LDG.128 --------
// 256 threads = 8 warps; warp w handles row blockIdx.x*8 + w. Each lane owns
// 4 words (128 bits / 128-float segment). Phase 1 exits early on saturation.
__global__ __launch_bounds__(256)
void fused_hop_kernel(int phase, float* __restrict__ out_final) {
    const uint4* Mv = (const uint4*)(phase ? g_A2 : g_A);

    const int tid  = threadIdx.x;
    const int wid  = tid >> 5;
    const int lane = tid & 31;
    const int i    = blockIdx.x * 8 + wid;

    __shared__ float          vsh[4096];
    __shared__ float          psum[256];
    __shared__ float          seg[32];
    __shared__ unsigned short list[8][WCAP];

    // ---- stage the angle vector (+ per-128 segment sums) ----
    {
        float s = 0.f;
        if (phase) {
            #pragma unroll
            for (int q = 0; q < 4; q++) {
                float4 v = *(const float4*)&g_av2[tid * 16 + q * 4];
                *(float4*)&vsh[tid * 16 + q * 4] = v;
                s += (v.x + v.y) + (v.z + v.w);
            }
        } else {
            #pragma unroll
            for (int q = 0; q < 16; q++) {
                int idx = tid * 16 + q;
                float v = g_a0[idx] +
                          (float)((double)g_stepq[idx] * (1.0 / 4294967296.0));
                vsh[idx] = v;
                s += v;
            }
        }
        psum[tid] = s;
    }
    __syncthreads();
    if (tid < 32) {
        float s = 0.f;
        #pragma unroll
        for (int q = 0; q < 8; q++) s += psum[tid * 8 + q];
        seg[tid] = s;
    }
    __syncthreads();

    // ---- build neighbor list for row i (warp scan, no atomics) ----
    uint4 aw = ((const uint4*)&g_A[i * NW])[lane];
    int nb = popc4(aw);
    int off = nb;
    #pragma unroll
    for (int d = 1; d < 32; d <<= 1) {
        int v = __shfl_up_sync(0xffffffffu, off, d);
        if (lane >= d) off += v;
    }
    const int total = __shfl_sync(0xffffffffu, off, 31);
    int pos = off - nb;
    unsigned short* L = list[wid];
    if (total <= WCAP) {
        unsigned mm; int jb;
        mm = aw.x; jb = lane * 128;
        while (mm) { int b = __ffs((int)mm) - 1; mm &= mm - 1; L[pos++] = (unsigned short)(jb + b); }
        mm = aw.y; jb = lane * 128 + 32;
        while (mm) { int b = __ffs((int)mm) - 1; mm &= mm - 1; L[pos++] = (unsigned short)(jb + b); }
        mm = aw.z; jb = lane * 128 + 64;
        while (mm) { int b = __ffs((int)mm) - 1; mm &= mm - 1; L[pos++] = (unsigned short)(jb + b); }
        mm = aw.w; jb = lane * 128 + 96;
        while (mm) { int b = __ffs((int)mm) - 1; mm &= mm - 1; L[pos++] = (unsigned short)(jb + b); }
    }
    __syncwarp();

    // ---- OR over neighbor rows ----
    uint4 acc = make_uint4(0u, 0u, 0u, 0u);
    if (total <= WCAP) {
        const int c = total;
        int j = 0;
        if (phase) {
            bool done = false;
            for (; j + 4 <= c && !done; j += 4) {
                uint4 q0 = __ldg(&Mv[(int)L[j]     * 32 + lane]);
                uint4 q1 = __ldg(&Mv[(int)L[j + 1] * 32 + lane]);
                uint4 q2 = __ldg(&Mv[(int)L[j + 2] * 32 + lane]);
                uint4 q3 = __ldg(&Mv[(int)L[j + 3] * 32 + lane]);
                acc.x |= (q0.x | q1.x) | (q2.x | q3.x);
                acc.y |= (q0.y | q1.y) | (q2.y | q3.y);
                acc.z |= (q0.z | q1.z) | (q2.z | q3.z);
                acc.w |= (q0.w | q1.w) | (q2.w | q3.w);
                unsigned sat = acc.x & acc.y & acc.z & acc.w;
                done = __all_sync(0xffffffffu, sat == 0xffffffffu);
            }
            if (!done)
                for (; j < c; j++) {
                    uint4 q = __ldg(&Mv[(int)L[j] * 32 + lane]);
                    acc.x |= q.x; acc.y |= q.y; acc.z |= q.z; acc.w |= q.w;
                }
        } else {
            for (; j + 4 <= c; j += 4) {
                uint4 q0 = __ldg(&Mv[(int)L[j]     * 32 + lane]);
                uint4 q1 = __ldg(&Mv[(int)L[j + 1] * 32 + lane]);
                uint4 q2 = __ldg(&Mv[(int)L[j + 2] * 32 + lane]);
                uint4 q3 = __ldg(&Mv[(int)L[j + 3] * 32 + lane]);
                acc.x |= (q0.x | q1.x) | (q2.x | q3.x);
                acc.y |= (q0.y | q1.y) | (q2.y | q3.y);
                acc.z |= (q0.z | q1.z) | (q2.z | q3.z);
                acc.w |= (q0.w | q1.w) | (q2.w | q3.w);
            }
            for (; j < c; j++) {
                uint4 q = __ldg(&Mv[(int)L[j] * 32 + lane]);
                acc.x |= q.x; acc.y |= q.y; acc.z |= q.z; acc.w |= q.w;
            }
        }
    } else {
        // fallback: broadcast each adjacency word and expand (never expected)
        #pragma unroll
        for (int c4 = 0; c4 < 4; c4++) {
            unsigned mycomp = (c4 == 0) ? aw.x : (c4 == 1) ? aw.y : (c4 == 2) ? aw.z : aw.w;
            for (int src = 0; src < 32; src++) {
                unsigned mm = __shfl_sync(0xffffffffu, mycomp, src);
                int jb = src * 128 + c4 * 32;
                while (mm) {
                    int b = __ffs((int)mm) - 1; mm &= mm - 1;
                    uint4 q = __ldg(&Mv[(jb + b) * 32 + lane]);
                    acc.x |= q.x; acc.y |= q.y; acc.z |= q.z; acc.w |= q.w;
                }
            }
        }
    }

    if (!phase) ((uint4*)&g_A2[i * NW])[lane] = acc;

    // ---- gated sum over this lane's 128-float segment ----
    const float* base = vsh + lane * 128;
    int pc = popc4(acc);
    float sv;
    if (pc > 64) {
        sv = seg[lane];
        unsigned m;
        m = ~acc.x; while (m) { int b = __ffs((int)m) - 1; m &= m - 1; sv -= base[b]; }
        m = ~acc.y; while (m) { int b = __ffs((int)m) - 1; m &= m - 1; sv -= base[32 + b]; }
        m = ~acc.z; while (m) { int b = __ffs((int)m) - 1; m &= m - 1; sv -= base[64 + b]; }
        m = ~acc.w; while (m) { int b = __ffs((int)m) - 1; m &= m - 1; sv -= base[96 + b]; }
    } else {
        sv = 0.f;
        unsigned m;
        m = acc.x; while (m) { int b = __ffs((int)m) - 1; m &= m - 1; sv += base[b]; }
        m = acc.y; while (m) { int b = __ffs((int)m) - 1; m &= m - 1; sv += base[32 + b]; }
        m = acc.z; while (m) { int b = __ffs((int)m) - 1; m &= m - 1; sv += base[64 + b]; }
        m = acc.w; while (m) { int b = __ffs((int)m) - 1; m &= m - 1; sv += base[96 + b]; }
    }
    #pragma unroll
    for (int o = 16; o; o >>= 1) sv += __shfl_down_sync(0xffffffffu, sv, o);

    if (lane == 0) {
        if (!phase) {
            float s1 = (float)((double)g_stepq[i] * (1.0 / 4294967296.0));
            float ns = s1 + 1.0986122886681098f * sv;            // ln 3
            g_step[i] = ns;
            g_av2[i]  = vsh[i] + ns;                              // a1[i] + step
        } else {
            out_final[i] = vsh[i] + g_step[i] + 1.3862943611198906f * sv; // ln 4
        }
    }
}

// ---------------- launch ----------------------------------------------------
extern "C" void kernel_launch(void* const* d_in, const int* in_sizes, int n_in,
                              void* d_out, int out_size) {
    const float* coeffs = (const float*)d_in[0];
    const void*  ei     = d_in[1];
    const float* W0     = (const float*)d_in[2];
    const float* b0     = (const float*)d_in[3];
    const float* W1     = (const float*)d_in[4];
    const float* W2     = (const float*)d_in[5];
    const float* W3     = (const float*)d_in[6];
    const float* b3     = (const float*)d_in[7];
    float* out = (float*)d_out;

    const int ne = in_sizes[1] / 2;

    const int prep_blocks = (N * NW + 3 * 16384) / 256 + 1;
    prep_kernel<<<prep_blocks, 256>>>(W0, W1, W2, ei);

    mlp_kernel<<<N / MLP_R, 128>>>(coeffs, b0, W3, b3);

    edge_kernel<<<(ne + 255) / 256, 256>>>(ei, ne);

    fused_hop_kernel<<<N / 8, 256>>>(0, out);
    fused_hop_kernel<<<N / 8, 256>>>(1, out);
}